// round 2
// baseline (speedup 1.0000x reference)
#include <cuda_runtime.h>

#define HH 768
#define WW 768
#define NB 512
#define C1N 32
#define C2N 64
#define IW 769            // integral image width/height (H+1)
#define FEAT 1600         // C2 * 5 * 5
#define FC1N 128
#define NCLS 4

// ---------------- scratch (no allocations allowed) ----------------
__device__ float g_buf1[C1N * HH * WW];        // conv1 output (32,768,768)
__device__ float g_integ[C2N * IW * IW];       // conv2 output -> integral image (64,769,769)
__device__ float g_flat[NB * FEAT];            // pooled features (512,1600)
__device__ float g_h1[NB * FC1N];              // fc1 output (512,128)

// ---------------- fused conv3x3 + bias + relu + bn ----------------
// Block: 32x4 threads. Tile: 32 wide x 16 tall. Each thread: 4 rows x OCC out-channels.
template <int IC, int OCC>
__global__ __launch_bounds__(128)
void conv_bn_kernel(const float* __restrict__ in,
                    const float* __restrict__ wgt,   // [OC][IC][3][3]
                    const float* __restrict__ bias,
                    const float* __restrict__ bng,
                    const float* __restrict__ bnb,
                    const float* __restrict__ bnm,
                    const float* __restrict__ bnv,
                    float* __restrict__ out,
                    int rowStride, int chanStride, int outOff)
{
    extern __shared__ float smem[];
    float* s_in = smem;                 // [IC][18][34]
    float* s_w  = smem + IC * 18 * 34;  // [9][IC][OCC]

    const int tx = threadIdx.x, ty = threadIdx.y;
    const int tid = ty * 32 + tx;
    const int bx0 = blockIdx.x * 32;
    const int by0 = blockIdx.y * 16;
    const int ocBase = blockIdx.z * OCC;

    // load input tile (with zero padding at image borders)
    for (int idx = tid; idx < IC * 18 * 34; idx += 128) {
        int ic = idx / (18 * 34);
        int r  = idx % (18 * 34);
        int yy = r / 34, xx = r % 34;
        int gy = by0 + yy - 1, gx = bx0 + xx - 1;
        float v = 0.f;
        if (gy >= 0 && gy < HH && gx >= 0 && gx < WW)
            v = in[(ic * HH + gy) * WW + gx];
        s_in[idx] = v;
    }
    // load weight chunk transposed to [tap][ic][oc]
    for (int idx = tid; idx < 9 * IC * OCC; idx += 128) {
        int tap = idx / (IC * OCC);
        int r   = idx % (IC * OCC);
        int ic  = r / OCC, oc = r % OCC;
        s_w[idx] = wgt[((ocBase + oc) * IC + ic) * 9 + tap];
    }
    __syncthreads();

    float acc[OCC][4];
#pragma unroll
    for (int oc = 0; oc < OCC; ++oc)
#pragma unroll
        for (int p = 0; p < 4; ++p) acc[oc][p] = 0.f;

#pragma unroll 1
    for (int ic = 0; ic < IC; ++ic) {
#pragma unroll
        for (int tap = 0; tap < 9; ++tap) {
            const int ky = tap / 3, kx = tap % 3;
            float v[4];
#pragma unroll
            for (int p = 0; p < 4; ++p)
                v[p] = s_in[(ic * 18 + (ty * 4 + p + ky)) * 34 + tx + kx];
            const float* wrow = &s_w[(tap * IC + ic) * OCC];
#pragma unroll
            for (int oc = 0; oc < OCC; ++oc) {
                const float wv = wrow[oc];
#pragma unroll
                for (int p = 0; p < 4; ++p) acc[oc][p] += v[p] * wv;
            }
        }
    }

#pragma unroll
    for (int oc = 0; oc < OCC; ++oc) {
        const int ocg = ocBase + oc;
        const float b  = bias[ocg];
        const float sc = bng[ocg] / sqrtf(bnv[ocg] + 1e-5f);
        const float sh = bnb[ocg] - bnm[ocg] * sc;
#pragma unroll
        for (int p = 0; p < 4; ++p) {
            float vv = acc[oc][p] + b;
            vv = vv > 0.f ? vv : 0.f;
            vv = vv * sc + sh;
            const int gy = by0 + ty * 4 + p;
            const int gx = bx0 + tx;
            out[ocg * chanStride + gy * rowStride + gx + outOff] = vv;
        }
    }
}

// ---------------- integral image ----------------
// Pass 1 (matches reference cumsum(axis=1) first): sequential down each column.
// Also writes the zero top row and zero left column.
__global__ void vscan_kernel()
{
    const int x = blockIdx.x * blockDim.x + threadIdx.x; // 0..768
    const int c = blockIdx.y;
    if (x >= IW) return;
    float* base = g_integ + (size_t)c * IW * IW;
    base[x] = 0.f; // top row (y=0)
    if (x == 0) {
        for (int y = 1; y < IW; ++y) base[(size_t)y * IW] = 0.f; // left col
        return;
    }
    float run = 0.f;
    for (int y = 1; y < IW; ++y) {
        run += base[(size_t)y * IW + x];
        base[(size_t)y * IW + x] = run;
    }
}

// Pass 2 (cumsum(axis=2)): sequential along each row.
__global__ void hscan_kernel()
{
    const int idx = blockIdx.x * blockDim.x + threadIdx.x;
    if (idx >= C2N * HH) return;
    const int c = idx / HH;
    const int y = idx % HH + 1;
    float* row = g_integ + ((size_t)c * IW + y) * IW;
    float run = 0.f;
    for (int x = 1; x < IW; ++x) {
        run += row[x];
        row[x] = run;
    }
}

// ---------------- ROI 5x5 pooling via integral image ----------------
__global__ void pool_kernel(const int* __restrict__ boxes)
{
    const int n = blockIdx.x;
    __shared__ int sy0[5], sy1[5], sx0[5], sx1[5];
    const int tid = threadIdx.x;
    if (tid < 5) {
        const int xmin = boxes[n * 4 + 0];
        const int ymin = boxes[n * 4 + 1];
        const int xmax = boxes[n * 4 + 2];
        const int ymax = boxes[n * 4 + 3];
        const int bh = ymax - ymin;
        const int bw = xmax - xmin;
        sy0[tid] = ymin + tid * bh / 5;
        sy1[tid] = ymin + ((tid + 1) * bh + 4) / 5;
        sx0[tid] = xmin + tid * bw / 5;
        sx1[tid] = xmin + ((tid + 1) * bw + 4) / 5;
    }
    __syncthreads();
    for (int e = tid; e < FEAT; e += blockDim.x) {
        const int c = e / 25, ij = e % 25, i = ij / 5, j = ij % 5;
        const float* I = g_integ + (size_t)c * IW * IW;
        const int y0 = sy0[i], y1 = sy1[i], x0 = sx0[j], x1 = sx1[j];
        const float s = I[(size_t)y1 * IW + x1] - I[(size_t)y0 * IW + x1]
                      - I[(size_t)y1 * IW + x0] + I[(size_t)y0 * IW + x0];
        const float area = (float)((y1 - y0) * (x1 - x0));
        g_flat[(size_t)n * FEAT + e] = s / area;
    }
}

// ---------------- fc1: (512,1600) @ (1600,128)^T + relu ----------------
// Block of 128 threads handles 4 boxes; thread o owns out-feature o.
__global__ __launch_bounds__(128)
void fc1_kernel(const float* __restrict__ w, const float* __restrict__ b)
{
    __shared__ float sf[4][FEAT];
    const int nb0 = blockIdx.x * 4;
    const int tid = threadIdx.x;
    for (int i = tid; i < 4 * FEAT; i += 128)
        sf[i / FEAT][i % FEAT] = g_flat[(size_t)(nb0 + i / FEAT) * FEAT + i % FEAT];
    __syncthreads();

    float acc0 = 0.f, acc1 = 0.f, acc2 = 0.f, acc3 = 0.f;
    const float* wr = w + (size_t)tid * FEAT;
    for (int k = 0; k < FEAT; k += 4) {
        const float4 wv = *(const float4*)(wr + k);
        acc0 += sf[0][k] * wv.x + sf[0][k + 1] * wv.y + sf[0][k + 2] * wv.z + sf[0][k + 3] * wv.w;
        acc1 += sf[1][k] * wv.x + sf[1][k + 1] * wv.y + sf[1][k + 2] * wv.z + sf[1][k + 3] * wv.w;
        acc2 += sf[2][k] * wv.x + sf[2][k + 1] * wv.y + sf[2][k + 2] * wv.z + sf[2][k + 3] * wv.w;
        acc3 += sf[3][k] * wv.x + sf[3][k + 1] * wv.y + sf[3][k + 2] * wv.z + sf[3][k + 3] * wv.w;
    }
    const float bb = b[tid];
    float r0 = acc0 + bb, r1 = acc1 + bb, r2 = acc2 + bb, r3 = acc3 + bb;
    g_h1[(size_t)(nb0 + 0) * FC1N + tid] = r0 > 0.f ? r0 : 0.f;
    g_h1[(size_t)(nb0 + 1) * FC1N + tid] = r1 > 0.f ? r1 : 0.f;
    g_h1[(size_t)(nb0 + 2) * FC1N + tid] = r2 > 0.f ? r2 : 0.f;
    g_h1[(size_t)(nb0 + 3) * FC1N + tid] = r3 > 0.f ? r3 : 0.f;
}

// ---------------- fc2: (512,128) @ (128,4)^T ----------------
__global__ void fc2_kernel(const float* __restrict__ w, const float* __restrict__ bias,
                           float* __restrict__ out)
{
    const int t = blockIdx.x * blockDim.x + threadIdx.x;
    if (t >= NB * NCLS) return;
    const int n = t / NCLS, o = t % NCLS;
    const float* h  = g_h1 + (size_t)n * FC1N;
    const float* wr = w + (size_t)o * FC1N;
    float acc = 0.f;
#pragma unroll 8
    for (int k = 0; k < FC1N; ++k) acc += h[k] * wr[k];
    out[t] = acc + bias[o];
}

// ---------------- launch ----------------
extern "C" void kernel_launch(void* const* d_in, const int* in_sizes, int n_in,
                              void* d_out, int out_size)
{
    const float* image  = (const float*)d_in[0];
    const int*   boxes  = (const int*)d_in[1];
    const float* c1w    = (const float*)d_in[2];
    const float* c1b    = (const float*)d_in[3];
    const float* bn1g   = (const float*)d_in[4];
    const float* bn1b   = (const float*)d_in[5];
    const float* bn1m   = (const float*)d_in[6];
    const float* bn1v   = (const float*)d_in[7];
    const float* c2w    = (const float*)d_in[8];
    const float* c2b    = (const float*)d_in[9];
    const float* bn2g   = (const float*)d_in[10];
    const float* bn2b   = (const float*)d_in[11];
    const float* bn2m   = (const float*)d_in[12];
    const float* bn2v   = (const float*)d_in[13];
    const float* fc1w   = (const float*)d_in[14];
    const float* fc1b   = (const float*)d_in[15];
    const float* fc2w   = (const float*)d_in[16];
    const float* fc2b   = (const float*)d_in[17];
    float* out = (float*)d_out;

    float *p_buf1, *p_integ;
    cudaGetSymbolAddress((void**)&p_buf1, g_buf1);
    cudaGetSymbolAddress((void**)&p_integ, g_integ);

    const int smem1 = (3 * 18 * 34 + 9 * 3 * 16) * 4;
    const int smem2 = (32 * 18 * 34 + 9 * 32 * 16) * 4;
    cudaFuncSetAttribute((const void*)conv_bn_kernel<32, 16>,
                         cudaFuncAttributeMaxDynamicSharedMemorySize, smem2);

    dim3 cblk(32, 4);

    // conv1 (3 -> 32), writes g_buf1 [32][768][768]
    conv_bn_kernel<3, 16><<<dim3(24, 48, 2), cblk, smem1>>>(
        image, c1w, c1b, bn1g, bn1b, bn1m, bn1v,
        p_buf1, WW, HH * WW, 0);

    // conv2 (32 -> 64), writes interior of g_integ at [c][y+1][x+1]
    conv_bn_kernel<32, 16><<<dim3(24, 48, 4), cblk, smem2>>>(
        p_buf1, c2w, c2b, bn2g, bn2b, bn2m, bn2v,
        p_integ, IW, IW * IW, IW + 1);

    // integral image: sequential vertical cumsum, then horizontal (matches ref order)
    vscan_kernel<<<dim3((IW + 255) / 256, C2N), 256>>>();
    hscan_kernel<<<(C2N * HH + 255) / 256, 256>>>();

    // ROI pooling -> g_flat
    pool_kernel<<<NB, 256>>>(boxes);

    // fc1 -> g_h1 (relu)
    fc1_kernel<<<NB / 4, 128>>>(fc1w, fc1b);

    // fc2 -> out
    fc2_kernel<<<(NB * NCLS + 255) / 256, 256>>>(fc2w, fc2b, out);
}

// round 3
// speedup vs baseline: 1.4398x; 1.4398x over previous
#include <cuda_runtime.h>

#define HH 768
#define WW 768
#define NB 512
#define C1N 32
#define C2N 64
#define IW 769            // integral image width/height (H+1)
#define FEAT 1600         // C2 * 5 * 5
#define FC1N 128
#define NCLS 4

// ---------------- scratch (no allocations allowed) ----------------
__device__ float g_buf1[C1N * HH * WW];        // conv1 output (32,768,768)
__device__ float g_integ[C2N * IW * IW];       // conv2 output -> integral image (64,769,769)
__device__ float g_flat[NB * FEAT];            // pooled features (512,1600)
__device__ float g_h1[NB * FC1N];              // fc1 output (512,128)

// ---------------- packed f32x2 helpers ----------------
typedef unsigned long long ull;

__device__ __forceinline__ ull ffma2(ull a, ull b, ull c) {
    ull d;
    asm("fma.rn.f32x2 %0, %1, %2, %3;" : "=l"(d) : "l"(a), "l"(b), "l"(c));
    return d;
}
__device__ __forceinline__ ull pack2(float lo, float hi) {
    ull r;
    asm("mov.b64 %0, {%1, %2};" : "=l"(r) : "f"(lo), "f"(hi));
    return r;
}
__device__ __forceinline__ void unpack2(ull v, float& lo, float& hi) {
    asm("mov.b64 {%0, %1}, %2;" : "=f"(lo), "=f"(hi) : "l"(v));
}

// ---------------- fused conv3x3 + bias + relu + bn ----------------
// Block: 32x4 threads. Tile: 32 wide x 16 tall. Each thread: 4 rows x OCC out-channels.
// Accumulators packed in f32x2 pairs along the OC dimension (FFMA2 = 2 MACs/slot).
template <int IC, int OCC>
__global__ __launch_bounds__(128)
void conv_bn_kernel(const float* __restrict__ in,
                    const float* __restrict__ wgt,   // [OC][IC][3][3]
                    const float* __restrict__ bias,
                    const float* __restrict__ bng,
                    const float* __restrict__ bnb,
                    const float* __restrict__ bnm,
                    const float* __restrict__ bnv,
                    float* __restrict__ out,
                    int rowStride, int chanStride, int outOff)
{
    extern __shared__ float smem[];
    float* s_in = smem;                 // [IC][18][34]
    float* s_w  = smem + IC * 18 * 34;  // [9][IC][OCC]  (oc consecutive -> LDS.64 pairs)

    const int tx = threadIdx.x, ty = threadIdx.y;
    const int tid = ty * 32 + tx;
    const int bx0 = blockIdx.x * 32;
    const int by0 = blockIdx.y * 16;
    const int ocBase = blockIdx.z * OCC;

    // load input tile (with zero padding at image borders)
    for (int idx = tid; idx < IC * 18 * 34; idx += 128) {
        int ic = idx / (18 * 34);
        int r  = idx % (18 * 34);
        int yy = r / 34, xx = r % 34;
        int gy = by0 + yy - 1, gx = bx0 + xx - 1;
        float v = 0.f;
        if (gy >= 0 && gy < HH && gx >= 0 && gx < WW)
            v = in[(ic * HH + gy) * WW + gx];
        s_in[idx] = v;
    }
    // load weight chunk transposed to [tap][ic][oc]
    for (int idx = tid; idx < 9 * IC * OCC; idx += 128) {
        int tap = idx / (IC * OCC);
        int r   = idx % (IC * OCC);
        int ic  = r / OCC, oc = r % OCC;
        s_w[idx] = wgt[((ocBase + oc) * IC + ic) * 9 + tap];
    }
    __syncthreads();

    constexpr int OCP = OCC / 2;   // packed pairs
    ull acc[OCP][4];
#pragma unroll
    for (int op = 0; op < OCP; ++op)
#pragma unroll
        for (int p = 0; p < 4; ++p) acc[op][p] = 0ull;   // (0.f, 0.f)

#pragma unroll 1
    for (int ic = 0; ic < IC; ++ic) {
#pragma unroll
        for (int tap = 0; tap < 9; ++tap) {
            const int ky = tap / 3, kx = tap % 3;
            ull vv[4];
#pragma unroll
            for (int p = 0; p < 4; ++p) {
                float v = s_in[(ic * 18 + (ty * 4 + p + ky)) * 34 + tx + kx];
                vv[p] = pack2(v, v);
            }
            const ull* wrow = (const ull*)&s_w[(tap * IC + ic) * OCC];
#pragma unroll
            for (int op = 0; op < OCP; ++op) {
                const ull w2 = wrow[op];
#pragma unroll
                for (int p = 0; p < 4; ++p)
                    acc[op][p] = ffma2(vv[p], w2, acc[op][p]);
            }
        }
    }

#pragma unroll
    for (int op = 0; op < OCP; ++op) {
#pragma unroll
        for (int half = 0; half < 2; ++half) {
            const int ocg = ocBase + op * 2 + half;
            const float b  = bias[ocg];
            const float sc = bng[ocg] / sqrtf(bnv[ocg] + 1e-5f);
            const float sh = bnb[ocg] - bnm[ocg] * sc;
#pragma unroll
            for (int p = 0; p < 4; ++p) {
                float lo, hi;
                unpack2(acc[op][p], lo, hi);
                float vv = (half ? hi : lo) + b;
                vv = vv > 0.f ? vv : 0.f;
                vv = vv * sc + sh;
                const int gy = by0 + ty * 4 + p;
                const int gx = bx0 + tx;
                out[ocg * chanStride + gy * rowStride + gx + outOff] = vv;
            }
        }
    }
}

// ---------------- integral image ----------------
// Pass 1 (matches reference cumsum(axis=1) first): sequential down each column.
// Also writes the zero top row and zero left column. Coalesced across columns.
__global__ void vscan_kernel()
{
    const int x = blockIdx.x * blockDim.x + threadIdx.x; // 0..768
    const int c = blockIdx.y;
    if (x >= IW) return;
    float* base = g_integ + (size_t)c * IW * IW;
    base[x] = 0.f; // top row (y=0)
    if (x == 0) {
        for (int y = 1; y < IW; ++y) base[(size_t)y * IW] = 0.f; // left col
        return;
    }
    float run = 0.f;
    for (int y = 1; y < IW; ++y) {
        run += base[(size_t)y * IW + x];
        base[(size_t)y * IW + x] = run;
    }
}

// Pass 2 (cumsum(axis=2)): warp per row, 24 coalesced chunks of 32,
// intra-warp inclusive shuffle scan + serial carry.
__global__ void hscan_kernel()
{
    const int warp = (blockIdx.x * blockDim.x + threadIdx.x) >> 5;
    const int lane = threadIdx.x & 31;
    if (warp >= C2N * HH) return;
    const int c = warp / HH;
    const int y = warp % HH + 1;
    float* row = g_integ + ((size_t)c * IW + y) * IW;

    float carry = 0.f;
#pragma unroll 1
    for (int k = 0; k < 24; ++k) {
        float v = row[1 + k * 32 + lane];
#pragma unroll
        for (int d = 1; d < 32; d <<= 1) {
            float n = __shfl_up_sync(0xFFFFFFFFu, v, d);
            if (lane >= d) v += n;
        }
        v += carry;
        row[1 + k * 32 + lane] = v;
        carry = __shfl_sync(0xFFFFFFFFu, v, 31);
    }
}

// ---------------- ROI 5x5 pooling via integral image ----------------
__global__ void pool_kernel(const int* __restrict__ boxes)
{
    const int n = blockIdx.x;
    __shared__ int sy0[5], sy1[5], sx0[5], sx1[5];
    const int tid = threadIdx.x;
    if (tid < 5) {
        const int xmin = boxes[n * 4 + 0];
        const int ymin = boxes[n * 4 + 1];
        const int xmax = boxes[n * 4 + 2];
        const int ymax = boxes[n * 4 + 3];
        const int bh = ymax - ymin;
        const int bw = xmax - xmin;
        sy0[tid] = ymin + tid * bh / 5;
        sy1[tid] = ymin + ((tid + 1) * bh + 4) / 5;
        sx0[tid] = xmin + tid * bw / 5;
        sx1[tid] = xmin + ((tid + 1) * bw + 4) / 5;
    }
    __syncthreads();
    for (int e = tid; e < FEAT; e += blockDim.x) {
        const int c = e / 25, ij = e % 25, i = ij / 5, j = ij % 5;
        const float* I = g_integ + (size_t)c * IW * IW;
        const int y0 = sy0[i], y1 = sy1[i], x0 = sx0[j], x1 = sx1[j];
        const float s = I[(size_t)y1 * IW + x1] - I[(size_t)y0 * IW + x1]
                      - I[(size_t)y1 * IW + x0] + I[(size_t)y0 * IW + x0];
        const float area = (float)((y1 - y0) * (x1 - x0));
        g_flat[(size_t)n * FEAT + e] = s / area;
    }
}

// ---------------- fc1: (512,1600) @ (1600,128)^T + relu ----------------
__global__ __launch_bounds__(128)
void fc1_kernel(const float* __restrict__ w, const float* __restrict__ b)
{
    __shared__ float sf[4][FEAT];
    const int nb0 = blockIdx.x * 4;
    const int tid = threadIdx.x;
    for (int i = tid; i < 4 * FEAT; i += 128)
        sf[i / FEAT][i % FEAT] = g_flat[(size_t)(nb0 + i / FEAT) * FEAT + i % FEAT];
    __syncthreads();

    float acc0 = 0.f, acc1 = 0.f, acc2 = 0.f, acc3 = 0.f;
    const float* wr = w + (size_t)tid * FEAT;
    for (int k = 0; k < FEAT; k += 4) {
        const float4 wv = *(const float4*)(wr + k);
        acc0 += sf[0][k] * wv.x + sf[0][k + 1] * wv.y + sf[0][k + 2] * wv.z + sf[0][k + 3] * wv.w;
        acc1 += sf[1][k] * wv.x + sf[1][k + 1] * wv.y + sf[1][k + 2] * wv.z + sf[1][k + 3] * wv.w;
        acc2 += sf[2][k] * wv.x + sf[2][k + 1] * wv.y + sf[2][k + 2] * wv.z + sf[2][k + 3] * wv.w;
        acc3 += sf[3][k] * wv.x + sf[3][k + 1] * wv.y + sf[3][k + 2] * wv.z + sf[3][k + 3] * wv.w;
    }
    const float bb = b[tid];
    float r0 = acc0 + bb, r1 = acc1 + bb, r2 = acc2 + bb, r3 = acc3 + bb;
    g_h1[(size_t)(nb0 + 0) * FC1N + tid] = r0 > 0.f ? r0 : 0.f;
    g_h1[(size_t)(nb0 + 1) * FC1N + tid] = r1 > 0.f ? r1 : 0.f;
    g_h1[(size_t)(nb0 + 2) * FC1N + tid] = r2 > 0.f ? r2 : 0.f;
    g_h1[(size_t)(nb0 + 3) * FC1N + tid] = r3 > 0.f ? r3 : 0.f;
}

// ---------------- fc2: (512,128) @ (128,4)^T ----------------
__global__ void fc2_kernel(const float* __restrict__ w, const float* __restrict__ bias,
                           float* __restrict__ out)
{
    const int t = blockIdx.x * blockDim.x + threadIdx.x;
    if (t >= NB * NCLS) return;
    const int n = t / NCLS, o = t % NCLS;
    const float* h  = g_h1 + (size_t)n * FC1N;
    const float* wr = w + (size_t)o * FC1N;
    float acc = 0.f;
#pragma unroll 8
    for (int k = 0; k < FC1N; ++k) acc += h[k] * wr[k];
    out[t] = acc + bias[o];
}

// ---------------- launch ----------------
extern "C" void kernel_launch(void* const* d_in, const int* in_sizes, int n_in,
                              void* d_out, int out_size)
{
    const float* image  = (const float*)d_in[0];
    const int*   boxes  = (const int*)d_in[1];
    const float* c1w    = (const float*)d_in[2];
    const float* c1b    = (const float*)d_in[3];
    const float* bn1g   = (const float*)d_in[4];
    const float* bn1b   = (const float*)d_in[5];
    const float* bn1m   = (const float*)d_in[6];
    const float* bn1v   = (const float*)d_in[7];
    const float* c2w    = (const float*)d_in[8];
    const float* c2b    = (const float*)d_in[9];
    const float* bn2g   = (const float*)d_in[10];
    const float* bn2b   = (const float*)d_in[11];
    const float* bn2m   = (const float*)d_in[12];
    const float* bn2v   = (const float*)d_in[13];
    const float* fc1w   = (const float*)d_in[14];
    const float* fc1b   = (const float*)d_in[15];
    const float* fc2w   = (const float*)d_in[16];
    const float* fc2b   = (const float*)d_in[17];
    float* out = (float*)d_out;

    float *p_buf1, *p_integ;
    cudaGetSymbolAddress((void**)&p_buf1, g_buf1);
    cudaGetSymbolAddress((void**)&p_integ, g_integ);

    const int smem1 = (3 * 18 * 34 + 9 * 3 * 16) * 4;
    const int smem2 = (32 * 18 * 34 + 9 * 32 * 16) * 4;
    cudaFuncSetAttribute((const void*)conv_bn_kernel<32, 16>,
                         cudaFuncAttributeMaxDynamicSharedMemorySize, smem2);

    dim3 cblk(32, 4);

    // conv1 (3 -> 32), writes g_buf1 [32][768][768]
    conv_bn_kernel<3, 16><<<dim3(24, 48, 2), cblk, smem1>>>(
        image, c1w, c1b, bn1g, bn1b, bn1m, bn1v,
        p_buf1, WW, HH * WW, 0);

    // conv2 (32 -> 64), writes interior of g_integ at [c][y+1][x+1]
    conv_bn_kernel<32, 16><<<dim3(24, 48, 4), cblk, smem2>>>(
        p_buf1, c2w, c2b, bn2g, bn2b, bn2m, bn2v,
        p_integ, IW, IW * IW, IW + 1);

    // integral image: vertical cumsum (coalesced serial), then warp-scan rows
    vscan_kernel<<<dim3((IW + 255) / 256, C2N), 256>>>();
    hscan_kernel<<<(C2N * HH * 32 + 255) / 256, 256>>>();

    // ROI pooling -> g_flat
    pool_kernel<<<NB, 256>>>(boxes);

    // fc1 -> g_h1 (relu)
    fc1_kernel<<<NB / 4, 128>>>(fc1w, fc1b);

    // fc2 -> out
    fc2_kernel<<<(NB * NCLS + 255) / 256, 256>>>(fc2w, fc2b, out);
}